// round 4
// baseline (speedup 1.0000x reference)
#include <cuda_runtime.h>
#include <cstdint>
#include <math_constants.h>

#define BATCH 16
#define CDIM  2048
#define TDIM  8192
#define KEEP  64

// ---- work decomposition ----
constexpr int NTHR    = 256;                 // 8 warps
constexpr int TITEM   = 128;                 // t per item
constexpr int T4      = TITEM / 4;           // 32 float4 lanes (one warp wide)
constexpr int CSEGS   = 8;                   // c segments per (b,tchunk)
constexpr int CSEG_SZ = CDIM / CSEGS;        // 256
constexpr int CPW     = CSEG_SZ / 8;         // 32 c-rows per warp
constexpr int NTCH    = TDIM / TITEM;        // 64 t-chunks per batch
constexpr int ITEMS   = BATCH * NTCH * CSEGS;// 8192
constexpr int GRID    = 304;                 // 2 blocks per SM on 152 SMs
constexpr int SEG     = TDIM / NTHR;         // 32 values/thread in topk

// Scratch (allocation-free rule: __device__ globals; zero-init, self-resetting)
__device__ float    g_part[BATCH * CSEGS * TDIM];  // 4 MB partials (L2-resident)
__device__ float    g_attn[BATCH * TDIM];
__device__ int      g_idx [BATCH * KEEP];
__device__ float    g_val [BATCH * KEEP];
__device__ unsigned g_tc  [BATCH * NTCH];          // per (b,tchunk) arrival ctr
__device__ unsigned g_bc  [BATCH];                 // per batch tchunk-done ctr

__global__ __launch_bounds__(NTHR)
void attn_topk_kernel(const float* __restrict__ x,
                      const float* __restrict__ w,
                      const float* __restrict__ bias)
{
    __shared__ float  ws[CDIM];                  // 8 KB
    __shared__ float4 red[7 * T4];               // 3.5 KB
    __shared__ float  sv[TDIM];                  // 32 KB (topk working copy)
    __shared__ float  lmax[NTHR];
    __shared__ int    lidx[NTHR];
    __shared__ float  wmax[NTHR / 32];
    __shared__ int    widx[NTHR / 32];
    __shared__ int    s_sel;
    __shared__ int    s_flag;

    const int tid  = threadIdx.x;
    const int wid  = tid >> 5;
    const int lane = tid & 31;
    const float bb = bias[0];

    for (int i = tid; i < CDIM; i += NTHR) ws[i] = w[i];
    __syncthreads();

    // ---- streamed matvec over fine items (b-major for early batch completion) ----
    for (int it = blockIdx.x; it < ITEMS; it += GRID) {
        const int b    = it >> 9;                // / (NTCH*CSEGS)
        const int r    = it & 511;
        const int tch  = r >> 3;
        const int cseg = r & 7;

        const float4* __restrict__ x4 =
            reinterpret_cast<const float4*>(x) + (size_t)b * CDIM * (TDIM / 4);
        const int t4g  = tch * T4 + lane;        // global float4 t index
        const int cbeg = cseg * CSEG_SZ + wid * CPW;

        float4 acc = make_float4(0.f, 0.f, 0.f, 0.f);
        #pragma unroll 8
        for (int cc = 0; cc < CPW; ++cc) {
            const int c = cbeg + cc;
            const float  wv = ws[c];
            const float4 xv = __ldcs(&x4[(size_t)c * (TDIM / 4) + t4g]);
            acc.x = fmaf(xv.x, wv, acc.x);
            acc.y = fmaf(xv.y, wv, acc.y);
            acc.z = fmaf(xv.z, wv, acc.z);
            acc.w = fmaf(xv.w, wv, acc.w);
        }

        if (wid > 0) red[(wid - 1) * T4 + lane] = acc;
        __syncthreads();

        if (wid == 0) {
            #pragma unroll
            for (int p = 0; p < 7; ++p) {
                const float4 q = red[p * T4 + lane];
                acc.x += q.x; acc.y += q.y; acc.z += q.z; acc.w += q.w;
            }
            float4* __restrict__ p4 = reinterpret_cast<float4*>(g_part);
            p4[(size_t)(b * CSEGS + cseg) * (TDIM / 4) + tch * T4 + lane] = acc;
            if (lane == 0) {
                __threadfence();
                const unsigned old = atomicAdd(&g_tc[b * NTCH + tch], 1u);
                s_flag = (old == CSEGS - 1);
            }
        }
        __syncthreads();

        int do_topk = 0;
        if (s_flag) {
            // ---- final reduce for (b, tch): deterministic cseg order ----
            if (tid < TITEM) {
                const int t = tch * TITEM + tid;
                float s = bb;
                #pragma unroll
                for (int sseg = 0; sseg < CSEGS; ++sseg)
                    s += __ldcg(&g_part[(size_t)(b * CSEGS + sseg) * TDIM + t]);
                g_attn[(size_t)b * TDIM + t] = s;
            }
            __syncthreads();
            if (tid == 0) {
                __threadfence();
                const unsigned old = atomicAdd(&g_bc[b], 1u);
                s_flag = (old == NTCH - 1);
            }
            __syncthreads();
            do_topk = s_flag;
        }
        if (!do_topk) { __syncthreads(); continue; }

        // ---- top-64 for batch b ----
        {
            const float* __restrict__ a = g_attn + (size_t)b * TDIM;
            for (int i = tid; i < TDIM; i += NTHR) sv[i] = __ldcg(&a[i]);
        }
        __syncthreads();

        const int base = tid * SEG;
        {
            float bm = -CUDART_INF_F; int bi = 0;
            #pragma unroll
            for (int i = 0; i < SEG; ++i) {
                const float v = sv[base + i];
                if (v > bm) { bm = v; bi = base + i; }   // strict > -> lowest index
            }
            lmax[tid] = bm; lidx[tid] = bi;
        }
        __syncthreads();

        for (int k = 0; k < KEEP; ++k) {
            float v  = lmax[tid];
            int   id = lidx[tid];
            #pragma unroll
            for (int off = 16; off; off >>= 1) {
                const float ov = __shfl_down_sync(0xffffffffu, v, off);
                const int   oi = __shfl_down_sync(0xffffffffu, id, off);
                if (ov > v || (ov == v && oi < id)) { v = ov; id = oi; }
            }
            if (lane == 0) { wmax[wid] = v; widx[wid] = id; }
            __syncthreads();

            if (tid == 0) {
                float bv = wmax[0]; int bI = widx[0];
                #pragma unroll
                for (int g = 1; g < NTHR / 32; ++g) {
                    const float ov = wmax[g]; const int oi = widx[g];
                    if (ov > bv || (ov == bv && oi < bI)) { bv = ov; bI = oi; }
                }
                g_idx[b * KEEP + k] = bI;
                g_val[b * KEEP + k] = bv;
                s_sel = bI;
                sv[bI] = -CUDART_INF_F;
            }
            __syncthreads();

            const int sel = s_sel;
            if ((sel / SEG) == tid) {
                float bm = -CUDART_INF_F; int bi = 0;
                #pragma unroll
                for (int i = 0; i < SEG; ++i) {
                    const float vv = sv[base + i];
                    if (vv > bm) { bm = vv; bi = base + i; }
                }
                lmax[tid] = bm; lidx[tid] = bi;
            }
            __syncthreads();
        }

        // reset this batch's counters for the next graph replay
        if (tid < NTCH) g_tc[b * NTCH + tid] = 0;
        if (tid == 0)   g_bc[b] = 0;
        __syncthreads();
    }
}

// ---------------- Kernel 2: gather latents + write indices ----------------
__global__ __launch_bounds__(256)
void gather_kernel(const float* __restrict__ x, float* __restrict__ out,
                   int write_indices)
{
    const int b = blockIdx.y;
    const int k = blockIdx.x;
    const int t = g_idx[b * KEEP + k];
    const float v = g_val[b * KEEP + k];
    const float scale = v + (1.0f - v);          // match reference rounding exactly

    const float* __restrict__ xp = x + (size_t)b * CDIM * TDIM + t;
    float* __restrict__ op = out + ((size_t)b * KEEP + k) * CDIM;

    float r[8];
    #pragma unroll
    for (int j = 0; j < 8; ++j) {
        const int c = threadIdx.x + j * 256;
        r[j] = __ldcs(xp + (size_t)c * TDIM);
    }
    #pragma unroll
    for (int j = 0; j < 8; ++j) {
        const int c = threadIdx.x + j * 256;
        op[c] = r[j] * scale;
    }

    if (write_indices && threadIdx.x == 0)
        out[(size_t)BATCH * KEEP * CDIM + b * KEEP + k] = (float)t;
}

extern "C" void kernel_launch(void* const* d_in, const int* in_sizes, int n_in,
                              void* d_out, int out_size)
{
    const float* x    = (const float*)d_in[0];
    const float* w    = (const float*)d_in[1];
    const float* bias = (const float*)d_in[2];
    float* out = (float*)d_out;

    attn_topk_kernel<<<GRID, NTHR>>>(x, w, bias);

    const int lat_elems = BATCH * KEEP * CDIM;   // 2,097,152
    const int widx = (out_size >= lat_elems + BATCH * KEEP) ? 1 : 0;
    dim3 g2(KEEP, BATCH);                        // (64, 16)
    gather_kernel<<<g2, 256>>>(x, out, widx);
}

// round 5
// speedup vs baseline: 3.5868x; 3.5868x over previous
#include <cuda_runtime.h>
#include <cstdint>
#include <math_constants.h>

#define BATCH 16
#define CDIM  2048
#define TDIM  8192
#define KEEP  64

// ---- decomposition ----
constexpr int NTHR      = 512;                 // 16 warps
constexpr int GRID      = 304;                 // 2 blocks/SM on 152 SMs, all resident
constexpr int LANES     = 64;                  // float4 lanes per c-partition
constexpr int CPARTS    = 8;
constexpr int CSEG      = CDIM / CPARTS;       // 256
constexpr int TCHUNK    = LANES * 4;           // 256 t per attn unit
constexpr int UNITS_PER_B = TDIM / TCHUNK;     // 32
constexpr int ATTN_UNITS  = BATCH * UNITS_PER_B;   // 512
constexpr int GATHER_UNITS = BATCH * KEEP;         // 1024 (one k each)
constexpr int TOTAL_UNITS  = ATTN_UNITS + GATHER_UNITS;
constexpr int SEG       = TDIM / NTHR;         // 16 values/thread in topk

// Scratch (__device__ globals; zero-init, reset by last exiting block)
__device__ float    g_attn[BATCH * TDIM];
__device__ int      g_idx [BATCH * KEEP];
__device__ float    g_val [BATCH * KEEP];
__device__ unsigned g_q;                        // unified work queue
__device__ unsigned g_bc  [BATCH];              // attn units done per batch
__device__ unsigned g_ready[BATCH];             // topk published
__device__ unsigned g_done;                     // exited blocks

__global__ __launch_bounds__(NTHR, 2)
void fused_kernel(const float* __restrict__ x,
                  const float* __restrict__ w,
                  const float* __restrict__ bias,
                  float* __restrict__ out,
                  int write_indices)
{
    __shared__ union {
        struct { float ws[CDIM]; float4 red[(CPARTS - 1) * LANES]; } a; // 15 KB
        float sv[TDIM];                                                  // 32 KB
    } sm;
    __shared__ float    lmax[NTHR];
    __shared__ int      lidx[NTHR];
    __shared__ float    wmax[NTHR / 32];
    __shared__ int      widxs[NTHR / 32];
    __shared__ int      s_sel;
    __shared__ int      s_flag;
    __shared__ unsigned s_claim;

    const int tid  = threadIdx.x;
    const int wid  = tid >> 5;
    const int lane = tid & 31;
    const float bb = bias[0];

    for (;;) {
        if (tid == 0) s_claim = atomicAdd(&g_q, 1u);
        __syncthreads();
        const unsigned u = s_claim;
        if (u >= TOTAL_UNITS) break;

        if (u < ATTN_UNITS) {
            // ================= attn unit: (b, tch) -> 256 t, full c =================
            const int b   = u / UNITS_PER_B;       // b-major: batch 0 finishes first
            const int tch = u % UNITS_PER_B;

            // (re)load w into shared (union may have been clobbered by a topk)
            for (int i = tid; i < CDIM; i += NTHR) sm.a.ws[i] = w[i];
            __syncthreads();

            const int l64 = tid & (LANES - 1);
            const int cp  = tid / LANES;           // 0..7
            const int t4  = tch * LANES + l64;     // global float4 t index

            const float4* __restrict__ x4 =
                reinterpret_cast<const float4*>(x) + (size_t)b * CDIM * (TDIM / 4);

            float4 acc = make_float4(0.f, 0.f, 0.f, 0.f);
            const int cbeg = cp * CSEG;
            #pragma unroll 8
            for (int c = cbeg; c < cbeg + CSEG; ++c) {
                const float  wv = sm.a.ws[c];
                const float4 xv = __ldcs(&x4[(size_t)c * (TDIM / 4) + t4]);
                acc.x = fmaf(xv.x, wv, acc.x);
                acc.y = fmaf(xv.y, wv, acc.y);
                acc.z = fmaf(xv.z, wv, acc.z);
                acc.w = fmaf(xv.w, wv, acc.w);
            }

            if (cp > 0) sm.a.red[(cp - 1) * LANES + l64] = acc;
            __syncthreads();

            if (cp == 0) {
                #pragma unroll
                for (int p = 0; p < CPARTS - 1; ++p) {
                    const float4 q = sm.a.red[p * LANES + l64];
                    acc.x += q.x; acc.y += q.y; acc.z += q.z; acc.w += q.w;
                }
                float4 o = make_float4(acc.x + bb, acc.y + bb, acc.z + bb, acc.w + bb);
                reinterpret_cast<float4*>(g_attn + (size_t)b * TDIM)[t4] = o;
                __threadfence();                    // release (one per unit)
            }
            __syncthreads();

            if (tid == 0) {
                const unsigned old = atomicAdd(&g_bc[b], 1u);
                s_flag = (old == UNITS_PER_B - 1);
            }
            __syncthreads();
            if (!s_flag) continue;

            // ================= top-64 for batch b =================
            {
                const float* __restrict__ a = g_attn + (size_t)b * TDIM;
                for (int i = tid; i < TDIM; i += NTHR) sm.sv[i] = __ldcg(&a[i]);
            }
            __syncthreads();

            const int base = tid * SEG;
            {
                float bm = -CUDART_INF_F; int bi = 0;
                #pragma unroll
                for (int i = 0; i < SEG; ++i) {
                    const float v = sm.sv[base + i];
                    if (v > bm) { bm = v; bi = base + i; }  // strict > -> lowest idx
                }
                lmax[tid] = bm; lidx[tid] = bi;
            }
            __syncthreads();

            for (int k = 0; k < KEEP; ++k) {
                float v  = lmax[tid];
                int   id = lidx[tid];
                #pragma unroll
                for (int off = 16; off; off >>= 1) {
                    const float ov = __shfl_down_sync(0xffffffffu, v, off);
                    const int   oi = __shfl_down_sync(0xffffffffu, id, off);
                    if (ov > v || (ov == v && oi < id)) { v = ov; id = oi; }
                }
                if (lane == 0) { wmax[wid] = v; widxs[wid] = id; }
                __syncthreads();

                if (tid == 0) {
                    float bv = wmax[0]; int bI = widxs[0];
                    #pragma unroll
                    for (int g = 1; g < NTHR / 32; ++g) {
                        const float ov = wmax[g]; const int oi = widxs[g];
                        if (ov > bv || (ov == bv && oi < bI)) { bv = ov; bI = oi; }
                    }
                    g_idx[b * KEEP + k] = bI;
                    g_val[b * KEEP + k] = bv;
                    s_sel = bI;
                    sm.sv[bI] = -CUDART_INF_F;
                }
                __syncthreads();

                const int sel = s_sel;
                if ((sel / SEG) == tid) {
                    float bm = -CUDART_INF_F; int bi = 0;
                    #pragma unroll
                    for (int i = 0; i < SEG; ++i) {
                        const float vv = sm.sv[base + i];
                        if (vv > bm) { bm = vv; bi = base + i; }
                    }
                    lmax[tid] = bm; lidx[tid] = bi;
                }
                __syncthreads();
            }

            if (tid == 0) {                     // publish (one fence)
                __threadfence();
                atomicExch(&g_ready[b], 1u);
            }
            __syncthreads();
        } else {
            // ================= gather unit: (b, k) =================
            const unsigned g = u - ATTN_UNITS;
            const int b = g >> 6;               // b-major
            const int k = g & (KEEP - 1);

            if (tid == 0) {
                while (atomicAdd(&g_ready[b], 0u) == 0u) __nanosleep(200);
                __threadfence();                // acquire
            }
            __syncthreads();

            const int t   = g_idx[b * KEEP + k];
            const float v = g_val[b * KEEP + k];
            const float scale = v + (1.0f - v); // match reference rounding exactly

            const float* __restrict__ xp = x + (size_t)b * CDIM * TDIM + t;
            float* __restrict__ op = out + ((size_t)b * KEEP + k) * CDIM;

            float r[4];
            #pragma unroll
            for (int j = 0; j < 4; ++j) {
                const int c = tid + j * NTHR;
                r[j] = __ldcs(xp + (size_t)c * TDIM);
            }
            #pragma unroll
            for (int j = 0; j < 4; ++j) {
                const int c = tid + j * NTHR;
                op[c] = r[j] * scale;
            }
            if (write_indices && tid == 0)
                out[(size_t)BATCH * KEEP * CDIM + b * KEEP + k] = (float)t;
        }
    }

    // last exiting block resets all control state for the next graph replay
    if (tid == 0) {
        const unsigned d = atomicAdd(&g_done, 1u);
        if (d == GRID - 1) {
            g_q = 0;
            g_done = 0;
            #pragma unroll
            for (int i = 0; i < BATCH; ++i) { g_bc[i] = 0; g_ready[i] = 0; }
            __threadfence();
        }
    }
}

extern "C" void kernel_launch(void* const* d_in, const int* in_sizes, int n_in,
                              void* d_out, int out_size)
{
    const float* x    = (const float*)d_in[0];
    const float* w    = (const float*)d_in[1];
    const float* bias = (const float*)d_in[2];
    float* out = (float*)d_out;

    const int lat_elems = BATCH * KEEP * CDIM;   // 2,097,152
    const int widx = (out_size >= lat_elems + BATCH * KEEP) ? 1 : 0;

    fused_kernel<<<GRID, NTHR>>>(x, w, bias, out, widx);
}